// round 6
// baseline (speedup 1.0000x reference)
#include <cuda_runtime.h>
#include <math.h>

// ---------------------------------------------------------------------------
// SplatPushModel2:
//   side stream : k_chain  — ONE fully-resident kernel computing the entire
//                 dependent scalar chain m_swept -> existing -> dep_sum via
//                 software grid barriers (128 blocks x 128 thr).
//   main stream : k_swept  — out = occ*(1-swept); 8 float4/thread, ldcs/stcs.
//   join        : k_depadd — out += blur(dep_mask)*dep_norm over deposit tiles.
// Sigmoid cutoff CUT=16 -> dropped terms < 1.2e-7 (tol 1e-3).
// ---------------------------------------------------------------------------

#define NB    16
#define HW    1024
#define IMG   (HW*HW)
#define GBLK  8                 // chain blocks per batch
#define GTOT  (GBLK*NB)         // 128 total chain blocks (<= #SMs, 1/SM)

__device__ __constant__ float KW[9] = {
    0.00761439f, 0.03607498f, 0.10958593f, 0.21344431f, 0.26655960f,
    0.21344431f, 0.10958593f, 0.03607498f, 0.00761439f
};

__device__ float g_msw[NB], g_ext[NB], g_dsum[NB];
__device__ unsigned g_cnt = 0;      // barrier arrivals (self-resets)
__device__ unsigned g_gen = 0;      // barrier generation (monotonic)

struct Geo { float p0x, p0y, p1x, p1y, ux, uy, L; };

__device__ __forceinline__ float clampf(float v, float lo, float hi) {
    return fminf(fmaxf(v, lo), hi);
}

__device__ __forceinline__ Geo makeGeo(const float* as_, const float* ae_, int b) {
    Geo g;
    g.p0x = as_[b*3+0]; g.p0y = as_[b*3+1];
    g.p1x = ae_[b*3+0]; g.p1y = ae_[b*3+1];
    float dx = g.p1x - g.p0x, dy = g.p1y - g.p0y;
    g.L = sqrtf(dx*dx + dy*dy + 1e-8f);
    float inv = __fdividef(1.0f, g.L);
    g.ux = dx*inv; g.uy = dy*inv;
    return g;
}

// grid-wide barrier; all GTOT blocks fully resident (1 block/SM max).
__device__ __forceinline__ void gridbar() {
    __syncthreads();
    if (threadIdx.x == 0) {
        __threadfence();
        unsigned my = *(volatile unsigned*)&g_gen;
        if (atomicAdd(&g_cnt, 1) == GTOT - 1) {
            atomicExch(&g_cnt, 0);
            __threadfence();
            atomicAdd(&g_gen, 1);
        } else {
            while (*(volatile unsigned*)&g_gen == my) __nanosleep(64);
        }
        __threadfence();
    }
    __syncthreads();
}

// 128-thread block reduce; result on thread 0.
__device__ __forceinline__ float blockSum128(float v) {
    __shared__ float sred[4];
    #pragma unroll
    for (int o = 16; o > 0; o >>= 1) v += __shfl_down_sync(0xffffffffu, v, o);
    int lane = threadIdx.x & 31, wp = threadIdx.x >> 5;
    if (lane == 0) sred[wp] = v;
    __syncthreads();
    float r = 0.f;
    if (threadIdx.x == 0) r = sred[0] + sred[1] + sred[2] + sred[3];
    __syncthreads();
    return r;
}

// x-interval of { slo<=s<=shi, |r|<=R } on scanline y, frame anchored at P.
__device__ __forceinline__ bool rowInterval(float Px, float Py, float ux, float uy,
                                            float slo, float shi, float R, int y,
                                            int& xa, int& xb) {
    float dy = (float)y - Py;
    float A = uy * dy;
    float B = ux * dy;
    float dlo = -2048.f, dhi = 2048.f;
    if (fabsf(ux) > 1e-4f) {
        float i0 = (slo - A) / ux, i1 = (shi - A) / ux;
        dlo = fmaxf(dlo, fminf(i0, i1));
        dhi = fminf(dhi, fmaxf(i0, i1));
    } else if (A < slo - 0.25f || A > shi + 0.25f) return false;
    if (fabsf(uy) > 1e-4f) {
        float i0 = (B - R) / uy, i1 = (B + R) / uy;
        dlo = fmaxf(dlo, fminf(i0, i1));
        dhi = fminf(dhi, fmaxf(i0, i1));
    } else if (fabsf(B) > R + 0.25f) return false;
    xa = max(0,    (int)floorf(Px + dlo) - 1);
    xb = min(1023, (int)ceilf (Px + dhi) + 1);
    return xa <= xb;
}

// per-thread band-scan partial for one phase
template<int MODE>
__device__ float bandScan(const float* __restrict__ base, Geo g,
                          float pile, float extra, int blk) {
    const float WIDTH = 3.0f, CUT = 16.0f, EPS = 1e-8f;
    float Px, Py, slo, shi, R, s0;
    if (MODE == 0) {
        Px = g.p0x; Py = g.p0y;
        R = WIDTH + CUT + 0.5f;
        slo = -R; shi = g.L + R; s0 = 0.f;
    } else {
        Px = g.p1x; Py = g.p1y;
        s0 = (MODE == 2) ? extra : 0.f;
        R  = WIDTH + CUT + 0.5f;
        slo = s0 - CUT - 0.5f; shi = s0 + pile + CUT + 0.5f;
    }
    float ay = fminf(g.uy*slo, g.uy*shi) - fabsf(g.ux)*R;
    float by = fmaxf(g.uy*slo, g.uy*shi) + fabsf(g.ux)*R;
    int y0 = max(0,    (int)floorf(Py + ay) - 1);
    int y1 = min(1023, (int)ceilf (Py + by) + 1);

    float acc = 0.f;
    for (int y = y0 + blk; y <= y1; y += GBLK) {
        int xa, xb;
        if (!rowInterval(Px, Py, g.ux, g.uy, slo, shi, R, y, xa, xb)) continue;
        float yf = (float)y;
        const float* row = base + y*HW;
        for (int x = xa + (int)threadIdx.x; x <= xb; x += 128) {
            float xf = (float)x;
            if (MODE == 0) {
                float rx = xf - g.p0x, ry = yf - g.p0y;
                float t  = clampf(rx*g.ux + ry*g.uy, 0.f, g.L);
                float ddx = rx - t*g.ux, ddy = ry - t*g.uy;
                float d2 = ddx*ddx + ddy*ddy + EPS;
                float R0 = WIDTH + CUT;
                if (d2 < R0*R0) {
                    float dist = d2 * rsqrtf(d2);
                    acc += row[x] * __fdividef(1.f, 1.f + __expf(dist - WIDTH));
                }
            } else {
                float qx = xf - g.p1x, qy = yf - g.p1y;
                float s  = qx*g.ux + qy*g.uy;
                float r  = qy*g.ux - qx*g.uy;
                float ar = fabsf(r);
                if (s > s0 - CUT && s < s0 + pile + CUT && ar < WIDTH + CUT) {
                    float den = (1.f + __expf(s0 - s))
                              * (1.f + __expf(s - s0 - pile))
                              * (1.f + __expf(ar - WIDTH));
                    float rho = (MODE == 2) ? 1.f : row[x];
                    acc += rho * __fdividef(1.f, den);
                }
            }
        }
    }
    return acc;
}

// Whole scalar chain in one launch. grid (GBLK, NB), 128 threads, 1 block/SM.
__global__ __launch_bounds__(128, 1) void k_chain(const float* __restrict__ occ,
                                                  const float* __restrict__ as_,
                                                  const float* __restrict__ ae_) {
    int b   = blockIdx.y;
    int blk = blockIdx.x;
    Geo g = makeGeo(as_, ae_, b);
    const float* base = occ + b*IMG;

    // block (0,0) zeroes accumulators (visible to all after bar #1)
    if (blk == 0 && b == 0 && threadIdx.x < 3*NB) {
        float* acc0 = (threadIdx.x < NB) ? &g_msw[threadIdx.x] :
                      (threadIdx.x < 2*NB) ? &g_ext[threadIdx.x - NB]
                                           : &g_dsum[threadIdx.x - 2*NB];
        *acc0 = 0.f;
    }

    // phase 0 compute overlaps zeroing wait
    float p0 = bandScan<0>(base, g, 0.f, 0.f, blk);
    gridbar();                                   // zeroing done
    {
        float t0 = blockSum128(p0);
        if (threadIdx.x == 0 && t0 != 0.f) atomicAdd(&g_msw[b], t0);
    }
    gridbar();                                   // m_swept complete
    float pile = __ldcg(&g_msw[b]) * (1.0f/6.0f);

    float p1 = bandScan<1>(base, g, pile, 0.f, blk);
    {
        float t1 = blockSum128(p1);
        if (threadIdx.x == 0 && t1 != 0.f) atomicAdd(&g_ext[b], t1);
    }
    gridbar();                                   // existing complete
    float extra = __ldcg(&g_ext[b]) * (1.0f/6.0f);

    float p2 = bandScan<2>(base, g, pile, extra, blk);
    {
        float t2 = blockSum128(p2);
        if (threadIdx.x == 0 && t2 != 0.f) atomicAdd(&g_dsum[b], t2);
    }
    // dep_sum visible at kernel completion
}

// out = occ*(1-swept); 128x64 tiles, 256 threads, 8 float4/thread.
__global__ __launch_bounds__(256) void k_swept(const float* __restrict__ occ,
                                               const float* __restrict__ as_,
                                               const float* __restrict__ ae_,
                                               float* __restrict__ out) {
    const float WIDTH = 3.0f, CUT = 16.0f, EPS = 1e-8f;
    int b  = blockIdx.z;
    int w0 = blockIdx.x << 7;   // 0..896 step 128
    int h0 = blockIdx.y << 6;   // 0..960 step 64
    Geo g = makeGeo(as_, ae_, b);

    // capsule-distance tile cull
    float cx = w0 + 63.5f, cy = h0 + 31.5f;
    float rxc = cx - g.p0x, ryc = cy - g.p0y;
    float tc  = clampf(rxc*g.ux + ryc*g.uy, 0.f, g.L);
    float dcx = rxc - tc*g.ux, dcy = ryc - tc*g.uy;
    float Rt  = WIDTH + CUT + 72.0f;
    bool sw_act = (dcx*dcx + dcy*dcy) < Rt*Rt;

    int t  = threadIdx.x;
    int lw = (t & 31) << 2;    // col 0..124
    int lh = t >> 5;           // row 0..7; rows lh + k*8
    int gi = b*IMG + (h0 + lh)*HW + (w0 + lw);

    float4 v[8];
    #pragma unroll
    for (int k = 0; k < 8; k++)
        v[k] = __ldcs((const float4*)(occ + gi + k*8*HW));

    if (!sw_act) {
        #pragma unroll
        for (int k = 0; k < 8; k++)
            __stcs((float4*)(out + gi + k*8*HW), v[k]);
        return;
    }

    #pragma unroll
    for (int k = 0; k < 8; k++) {
        float y  = (float)(h0 + lh + k*8);
        float ry = y - g.p0y;
        float o[4];
        float* in = (float*)&v[k];
        #pragma unroll
        for (int j = 0; j < 4; j++) {
            float x  = (float)(w0 + lw + j);
            float rx = x - g.p0x;
            float tt = clampf(rx*g.ux + ry*g.uy, 0.f, g.L);
            float ddx = rx - tt*g.ux, ddy = ry - tt*g.uy;
            float d2 = ddx*ddx + ddy*ddy + EPS;
            float R0 = WIDTH + CUT;
            float sw = 0.f;
            if (d2 < R0*R0) {
                float dist = d2 * rsqrtf(d2);
                sw = __fdividef(1.f, 1.f + __expf(dist - WIDTH));
            }
            o[j] = in[j] * (1.f - sw);
        }
        __stcs((float4*)(out + gi + k*8*HW), make_float4(o[0], o[1], o[2], o[3]));
    }
}

// out += blur(dep_mask)*dep_norm over deposit tiles (32x32, on-device AABB).
__global__ __launch_bounds__(256) void k_depadd(float* __restrict__ out,
                                                const float* __restrict__ as_,
                                                const float* __restrict__ ae_) {
    const float WIDTH = 3.0f, CUT = 16.0f, EPS = 1e-8f;
    int b = blockIdx.y;
    Geo g = makeGeo(as_, ae_, b);
    float msw   = __ldcg(&g_msw[b]);
    float pile  = msw * (1.0f/6.0f);
    float extra = __ldcg(&g_ext[b]) * (1.0f/6.0f);
    float dnorm = __fdividef(msw, __ldcg(&g_dsum[b]) + EPS);

    // AABB of deposit band + blur margin
    const float M = CUT + 6.5f;
    float slo = extra - M, shi = extra + pile + M;
    float R   = WIDTH + M;
    float ax = g.ux*slo, bx = g.ux*shi;
    float ay = g.uy*slo, by = g.uy*shi;
    float xmin = g.p1x + fminf(ax, bx) - fabsf(g.uy)*R;
    float xmax = g.p1x + fmaxf(ax, bx) + fabsf(g.uy)*R;
    float ymin = g.p1y + fminf(ay, by) - fabsf(g.ux)*R;
    float ymax = g.p1y + fmaxf(ay, by) + fabsf(g.ux)*R;
    int tx0 = max(0, ((int)floorf(xmin)) >> 5);
    int ty0 = max(0, ((int)floorf(ymin)) >> 5);
    int tx1 = min(31, ((int)floorf(xmax)) >> 5);
    int ty1 = min(31, ((int)floorf(ymax)) >> 5);
    int nx = tx1 - tx0 + 1, ny = ty1 - ty0 + 1;
    if (nx <= 0 || ny <= 0) return;
    int nt = nx * ny;

    __shared__ float sd[40][41];
    __shared__ float sh[40][32];

    int t = threadIdx.x;
    for (int idx = blockIdx.x; idx < nt; idx += gridDim.x) {
        int tw = (tx0 + idx % nx) << 5;
        int th = (ty0 + idx / nx) << 5;

        float cx = tw + 15.5f, cy = th + 15.5f;
        float qx = cx - g.p1x, qy = cy - g.p1y;
        float s  = qx*g.ux + qy*g.uy;
        float r  = qy*g.ux - qx*g.uy;
        float he = 16.5f*(fabsf(g.ux) + fabsf(g.uy)) + 6.0f;
        bool active = (s + he > extra - CUT) && (s - he < extra + pile + CUT)
                   && (fabsf(r) - he < WIDTH + CUT);
        if (!active) continue;

        for (int i = t; i < 40*40; i += 256) {
            int r_ = i / 40, c_ = i - r_*40;
            int wx = tw + c_ - 4, hy = th + r_ - 4;
            float val = 0.f;
            if ((unsigned)wx < 1024u && (unsigned)hy < 1024u) {
                float px = (float)wx - g.p1x, py = (float)hy - g.p1y;
                float ss = px*g.ux + py*g.uy;
                float rr = py*g.ux - px*g.uy;
                float ar = fabsf(rr);
                if (ss > extra - CUT && ss < extra + pile + CUT && ar < WIDTH + CUT) {
                    float den = (1.f + __expf(extra - ss))
                              * (1.f + __expf(ss - extra - pile))
                              * (1.f + __expf(ar - WIDTH));
                    val = __fdividef(1.f, den);
                }
            }
            sd[r_][c_] = val;
        }
        __syncthreads();
        for (int i = t; i < 40*32; i += 256) {
            int r_ = i >> 5, c_ = i & 31;
            float a = 0.f;
            #pragma unroll
            for (int j = 0; j < 9; j++) a = fmaf(KW[j], sd[r_][c_ + j], a);
            sh[r_][c_] = a;
        }
        __syncthreads();
        for (int i = t; i < 32*32; i += 256) {
            int r_ = i >> 5, c_ = i & 31;
            float a = 0.f;
            #pragma unroll
            for (int j = 0; j < 9; j++) a = fmaf(KW[j], sh[r_ + j][c_], a);
            int gi = b*IMG + (th + r_)*HW + (tw + c_);
            out[gi] += a * dnorm;
        }
        __syncthreads();
    }
}

extern "C" void kernel_launch(void* const* d_in, const int* in_sizes, int n_in,
                              void* d_out, int out_size) {
    const float* occ = (const float*)d_in[0];
    const float* as_ = (const float*)d_in[1];
    const float* ae_ = (const float*)d_in[2];
    float* out = (float*)d_out;

    cudaStream_t side;
    cudaEvent_t e_fork, e_join;
    cudaStreamCreateWithFlags(&side, cudaStreamNonBlocking);
    cudaEventCreateWithFlags(&e_fork, cudaEventDisableTiming);
    cudaEventCreateWithFlags(&e_join, cudaEventDisableTiming);

    cudaEventRecord(e_fork, 0);
    cudaStreamWaitEvent(side, e_fork, 0);

    k_chain<<<dim3(GBLK, NB), 128, 0, side>>>(occ, as_, ae_);
    cudaEventRecord(e_join, side);

    k_swept<<<dim3(8, 16, NB), 256>>>(occ, as_, ae_, out);   // overlaps chain

    cudaStreamWaitEvent(0, e_join, 0);
    k_depadd<<<dim3(64, NB), 256>>>(out, as_, ae_);
}

// round 7
// speedup vs baseline: 1.3608x; 1.3608x over previous
#include <cuda_runtime.h>
#include <math.h>

// ---------------------------------------------------------------------------
// SplatPushModel2:
//   side stream : k_chain — ONE resident kernel (144 blk x 256 thr), whole
//                 dependent scalar chain via grid barriers. Warp-per-row,
//                 float4 band loads; phase 2 is compute-only.
//   main stream : k_swept — out = occ*(1-swept); 8 float4/thread, ldcs/stcs.
//   join        : k_depadd — out += blur(dep_mask)*dep_norm (deposit tiles).
// Sigmoid cutoff CUT=16 -> dropped terms < 1.2e-7 (tol 1e-3).
// ---------------------------------------------------------------------------

#define NB    16
#define HW    1024
#define IMG   (HW*HW)
#define GBLK  9                 // chain blocks per batch
#define GTOT  (GBLK*NB)         // 144 total chain blocks (<=148 SMs)
#define WPB   8                 // warps per chain block

__device__ __constant__ float KW[9] = {
    0.00761439f, 0.03607498f, 0.10958593f, 0.21344431f, 0.26655960f,
    0.21344431f, 0.10958593f, 0.03607498f, 0.00761439f
};

__device__ float g_msw[NB], g_ext[NB], g_dsum[NB];
__device__ unsigned g_cnt = 0;      // barrier arrivals (self-resets)
__device__ unsigned g_gen = 0;      // barrier generation (monotonic)

struct Geo { float p0x, p0y, p1x, p1y, ux, uy, L; };

__device__ __forceinline__ float clampf(float v, float lo, float hi) {
    return fminf(fmaxf(v, lo), hi);
}

__device__ __forceinline__ Geo makeGeo(const float* as_, const float* ae_, int b) {
    Geo g;
    g.p0x = as_[b*3+0]; g.p0y = as_[b*3+1];
    g.p1x = ae_[b*3+0]; g.p1y = ae_[b*3+1];
    float dx = g.p1x - g.p0x, dy = g.p1y - g.p0y;
    g.L = sqrtf(dx*dx + dy*dy + 1e-8f);
    float inv = __fdividef(1.0f, g.L);
    g.ux = dx*inv; g.uy = dy*inv;
    return g;
}

// grid-wide barrier; all GTOT blocks resident.
__device__ __forceinline__ void gridbar() {
    __syncthreads();
    if (threadIdx.x == 0) {
        __threadfence();
        unsigned my = *(volatile unsigned*)&g_gen;
        if (atomicAdd(&g_cnt, 1) == GTOT - 1) {
            atomicExch(&g_cnt, 0);
            __threadfence();
            atomicAdd(&g_gen, 1);
        } else {
            while (*(volatile unsigned*)&g_gen == my) __nanosleep(32);
        }
        __threadfence();
    }
    __syncthreads();
}

// x-interval of { slo<=s<=shi, |r|<=R } on scanline y, frame anchored at P.
__device__ __forceinline__ bool rowInterval(float Px, float Py, float ux, float uy,
                                            float slo, float shi, float R, int y,
                                            int& xa, int& xb) {
    float dy = (float)y - Py;
    float A = uy * dy;
    float B = ux * dy;
    float dlo = -2048.f, dhi = 2048.f;
    if (fabsf(ux) > 1e-4f) {
        float i0 = (slo - A) / ux, i1 = (shi - A) / ux;
        dlo = fmaxf(dlo, fminf(i0, i1));
        dhi = fminf(dhi, fmaxf(i0, i1));
    } else if (A < slo - 0.25f || A > shi + 0.25f) return false;
    if (fabsf(uy) > 1e-4f) {
        float i0 = (B - R) / uy, i1 = (B + R) / uy;
        dlo = fmaxf(dlo, fminf(i0, i1));
        dhi = fminf(dhi, fmaxf(i0, i1));
    } else if (fabsf(B) > R + 0.25f) return false;
    xa = max(0,    (int)floorf(Px + dlo) - 1);
    xb = min(1023, (int)ceilf (Px + dhi) + 1);
    return xa <= xb;
}

// one phase: warp-per-row band scan, float4 loads (MODE<2). Returns lane partial.
template<int MODE>
__device__ float bandScan(const float* __restrict__ base, Geo g,
                          float pile, float extra, int blk) {
    const float WIDTH = 3.0f, CUT = 16.0f, EPS = 1e-8f;
    float Px, Py, slo, shi, R, s0;
    if (MODE == 0) {
        Px = g.p0x; Py = g.p0y;
        R = WIDTH + CUT + 0.5f;
        slo = -R; shi = g.L + R; s0 = 0.f;
    } else {
        Px = g.p1x; Py = g.p1y;
        s0 = (MODE == 2) ? extra : 0.f;
        R  = WIDTH + CUT + 0.5f;
        slo = s0 - CUT - 0.5f; shi = s0 + pile + CUT + 0.5f;
    }
    float ay = fminf(g.uy*slo, g.uy*shi) - fabsf(g.ux)*R;
    float by = fmaxf(g.uy*slo, g.uy*shi) + fabsf(g.ux)*R;
    int y0 = max(0,    (int)floorf(Py + ay) - 1);
    int y1 = min(1023, (int)ceilf (Py + by) + 1);

    int wp   = threadIdx.x >> 5;          // 0..WPB-1
    int lane = threadIdx.x & 31;
    int wrow = blk*WPB + wp;              // warp slot in batch: 0..GBLK*WPB-1

    float acc = 0.f;
    for (int y = y0 + wrow; y <= y1; y += GBLK*WPB) {
        int xa, xb;
        if (!rowInterval(Px, Py, g.ux, g.uy, slo, shi, R, y, xa, xb)) continue;
        float yf = (float)y;
        const float* row = base + y*HW;
        int x4a = xa & ~3;
        for (int xs = x4a + lane*4; xs <= xb; xs += 128) {
            float rho[4] = {1.f, 1.f, 1.f, 1.f};
            if (MODE < 2) {
                float4 v = *(const float4*)(row + xs);
                rho[0]=v.x; rho[1]=v.y; rho[2]=v.z; rho[3]=v.w;
            }
            #pragma unroll
            for (int j = 0; j < 4; j++) {
                float xf = (float)(xs + j);
                if (MODE == 0) {
                    float rx = xf - g.p0x, ry = yf - g.p0y;
                    float t  = clampf(rx*g.ux + ry*g.uy, 0.f, g.L);
                    float ddx = rx - t*g.ux, ddy = ry - t*g.uy;
                    float d2 = ddx*ddx + ddy*ddy + EPS;
                    float R0 = WIDTH + CUT;
                    if (d2 < R0*R0) {
                        float dist = d2 * rsqrtf(d2);
                        acc += rho[j] * __fdividef(1.f, 1.f + __expf(dist - WIDTH));
                    }
                } else {
                    float qx = xf - g.p1x, qy = yf - g.p1y;
                    float s  = qx*g.ux + qy*g.uy;
                    float r  = qy*g.ux - qx*g.uy;
                    float ar = fabsf(r);
                    if (s > s0 - CUT && s < s0 + pile + CUT && ar < WIDTH + CUT) {
                        float den = (1.f + __expf(s0 - s))
                                  * (1.f + __expf(s - s0 - pile))
                                  * (1.f + __expf(ar - WIDTH));
                        acc += rho[j] * __fdividef(1.f, den);
                    }
                }
            }
        }
    }
    return acc;
}

// block-sum (256 thr) + atomic into dst
__device__ __forceinline__ void sumAdd256(float v, float* dst) {
    __shared__ float sred[WPB];
    #pragma unroll
    for (int o = 16; o > 0; o >>= 1) v += __shfl_down_sync(0xffffffffu, v, o);
    int lane = threadIdx.x & 31, wp = threadIdx.x >> 5;
    if (lane == 0) sred[wp] = v;
    __syncthreads();
    if (threadIdx.x == 0) {
        float t = 0.f;
        #pragma unroll
        for (int i = 0; i < WPB; i++) t += sred[i];
        if (t != 0.f) atomicAdd(dst, t);
    }
    __syncthreads();
}

// Whole scalar chain in one launch. grid (GBLK, NB), 256 threads.
__global__ __launch_bounds__(256) void k_chain(const float* __restrict__ occ,
                                               const float* __restrict__ as_,
                                               const float* __restrict__ ae_) {
    int b   = blockIdx.y;
    int blk = blockIdx.x;
    Geo g = makeGeo(as_, ae_, b);
    const float* base = occ + b*IMG;

    if (blk == 0 && b == 0 && threadIdx.x < 3*NB) {
        float* a0 = (threadIdx.x < NB) ? &g_msw[threadIdx.x] :
                    (threadIdx.x < 2*NB) ? &g_ext[threadIdx.x - NB]
                                         : &g_dsum[threadIdx.x - 2*NB];
        *a0 = 0.f;
    }

    float p0 = bandScan<0>(base, g, 0.f, 0.f, blk);  // overlaps zero-wait
    gridbar();                                       // zeroing visible
    sumAdd256(p0, &g_msw[b]);
    gridbar();                                       // m_swept complete
    float pile = __ldcg(&g_msw[b]) * (1.0f/6.0f);

    float p1 = bandScan<1>(base, g, pile, 0.f, blk);
    sumAdd256(p1, &g_ext[b]);
    gridbar();                                       // existing complete
    float extra = __ldcg(&g_ext[b]) * (1.0f/6.0f);

    float p2 = bandScan<2>(base, g, pile, extra, blk);   // no loads
    sumAdd256(p2, &g_dsum[b]);
}

// out = occ*(1-swept); 128x64 tiles, 256 threads, 8 float4/thread.
__global__ __launch_bounds__(256) void k_swept(const float* __restrict__ occ,
                                               const float* __restrict__ as_,
                                               const float* __restrict__ ae_,
                                               float* __restrict__ out) {
    const float WIDTH = 3.0f, CUT = 16.0f, EPS = 1e-8f;
    int b  = blockIdx.z;
    int w0 = blockIdx.x << 7;
    int h0 = blockIdx.y << 6;
    Geo g = makeGeo(as_, ae_, b);

    float cx = w0 + 63.5f, cy = h0 + 31.5f;
    float rxc = cx - g.p0x, ryc = cy - g.p0y;
    float tc  = clampf(rxc*g.ux + ryc*g.uy, 0.f, g.L);
    float dcx = rxc - tc*g.ux, dcy = ryc - tc*g.uy;
    float Rt  = WIDTH + CUT + 72.0f;
    bool sw_act = (dcx*dcx + dcy*dcy) < Rt*Rt;

    int t  = threadIdx.x;
    int lw = (t & 31) << 2;
    int lh = t >> 5;
    int gi = b*IMG + (h0 + lh)*HW + (w0 + lw);

    float4 v[8];
    #pragma unroll
    for (int k = 0; k < 8; k++)
        v[k] = __ldcs((const float4*)(occ + gi + k*8*HW));

    if (!sw_act) {
        #pragma unroll
        for (int k = 0; k < 8; k++)
            __stcs((float4*)(out + gi + k*8*HW), v[k]);
        return;
    }

    #pragma unroll
    for (int k = 0; k < 8; k++) {
        float y  = (float)(h0 + lh + k*8);
        float ry = y - g.p0y;
        float o[4];
        float* in = (float*)&v[k];
        #pragma unroll
        for (int j = 0; j < 4; j++) {
            float x  = (float)(w0 + lw + j);
            float rx = x - g.p0x;
            float tt = clampf(rx*g.ux + ry*g.uy, 0.f, g.L);
            float ddx = rx - tt*g.ux, ddy = ry - tt*g.uy;
            float d2 = ddx*ddx + ddy*ddy + EPS;
            float R0 = WIDTH + CUT;
            float sw = 0.f;
            if (d2 < R0*R0) {
                float dist = d2 * rsqrtf(d2);
                sw = __fdividef(1.f, 1.f + __expf(dist - WIDTH));
            }
            o[j] = in[j] * (1.f - sw);
        }
        __stcs((float4*)(out + gi + k*8*HW), make_float4(o[0], o[1], o[2], o[3]));
    }
}

// out += blur(dep_mask)*dep_norm over deposit tiles (32x32, on-device AABB).
__global__ __launch_bounds__(256) void k_depadd(float* __restrict__ out,
                                                const float* __restrict__ as_,
                                                const float* __restrict__ ae_) {
    const float WIDTH = 3.0f, CUT = 16.0f, EPS = 1e-8f;
    int b = blockIdx.y;
    Geo g = makeGeo(as_, ae_, b);
    float msw   = __ldcg(&g_msw[b]);
    float pile  = msw * (1.0f/6.0f);
    float extra = __ldcg(&g_ext[b]) * (1.0f/6.0f);
    float dnorm = __fdividef(msw, __ldcg(&g_dsum[b]) + EPS);

    const float M = CUT + 6.5f;
    float slo = extra - M, shi = extra + pile + M;
    float R   = WIDTH + M;
    float ax = g.ux*slo, bx = g.ux*shi;
    float ay = g.uy*slo, by = g.uy*shi;
    float xmin = g.p1x + fminf(ax, bx) - fabsf(g.uy)*R;
    float xmax = g.p1x + fmaxf(ax, bx) + fabsf(g.uy)*R;
    float ymin = g.p1y + fminf(ay, by) - fabsf(g.ux)*R;
    float ymax = g.p1y + fmaxf(ay, by) + fabsf(g.ux)*R;
    int tx0 = max(0, ((int)floorf(xmin)) >> 5);
    int ty0 = max(0, ((int)floorf(ymin)) >> 5);
    int tx1 = min(31, ((int)floorf(xmax)) >> 5);
    int ty1 = min(31, ((int)floorf(ymax)) >> 5);
    int nx = tx1 - tx0 + 1, ny = ty1 - ty0 + 1;
    if (nx <= 0 || ny <= 0) return;
    int nt = nx * ny;

    __shared__ float sd[40][41];
    __shared__ float sh[40][32];

    int t = threadIdx.x;
    for (int idx = blockIdx.x; idx < nt; idx += gridDim.x) {
        int tw = (tx0 + idx % nx) << 5;
        int th = (ty0 + idx / nx) << 5;

        float cx = tw + 15.5f, cy = th + 15.5f;
        float qx = cx - g.p1x, qy = cy - g.p1y;
        float s  = qx*g.ux + qy*g.uy;
        float r  = qy*g.ux - qx*g.uy;
        float he = 16.5f*(fabsf(g.ux) + fabsf(g.uy)) + 6.0f;
        bool active = (s + he > extra - CUT) && (s - he < extra + pile + CUT)
                   && (fabsf(r) - he < WIDTH + CUT);
        if (!active) continue;

        for (int i = t; i < 40*40; i += 256) {
            int r_ = i / 40, c_ = i - r_*40;
            int wx = tw + c_ - 4, hy = th + r_ - 4;
            float val = 0.f;
            if ((unsigned)wx < 1024u && (unsigned)hy < 1024u) {
                float px = (float)wx - g.p1x, py = (float)hy - g.p1y;
                float ss = px*g.ux + py*g.uy;
                float rr = py*g.ux - px*g.uy;
                float ar = fabsf(rr);
                if (ss > extra - CUT && ss < extra + pile + CUT && ar < WIDTH + CUT) {
                    float den = (1.f + __expf(extra - ss))
                              * (1.f + __expf(ss - extra - pile))
                              * (1.f + __expf(ar - WIDTH));
                    val = __fdividef(1.f, den);
                }
            }
            sd[r_][c_] = val;
        }
        __syncthreads();
        for (int i = t; i < 40*32; i += 256) {
            int r_ = i >> 5, c_ = i & 31;
            float a = 0.f;
            #pragma unroll
            for (int j = 0; j < 9; j++) a = fmaf(KW[j], sd[r_][c_ + j], a);
            sh[r_][c_] = a;
        }
        __syncthreads();
        for (int i = t; i < 32*32; i += 256) {
            int r_ = i >> 5, c_ = i & 31;
            float a = 0.f;
            #pragma unroll
            for (int j = 0; j < 9; j++) a = fmaf(KW[j], sh[r_ + j][c_], a);
            int gi = b*IMG + (th + r_)*HW + (tw + c_);
            out[gi] += a * dnorm;
        }
        __syncthreads();
    }
}

extern "C" void kernel_launch(void* const* d_in, const int* in_sizes, int n_in,
                              void* d_out, int out_size) {
    const float* occ = (const float*)d_in[0];
    const float* as_ = (const float*)d_in[1];
    const float* ae_ = (const float*)d_in[2];
    float* out = (float*)d_out;

    cudaStream_t side;
    cudaEvent_t e_fork, e_join;
    cudaStreamCreateWithFlags(&side, cudaStreamNonBlocking);
    cudaEventCreateWithFlags(&e_fork, cudaEventDisableTiming);
    cudaEventCreateWithFlags(&e_join, cudaEventDisableTiming);

    cudaEventRecord(e_fork, 0);
    cudaStreamWaitEvent(side, e_fork, 0);

    k_chain<<<dim3(GBLK, NB), 256, 0, side>>>(occ, as_, ae_);   // launched first
    cudaEventRecord(e_join, side);

    k_swept<<<dim3(8, 16, NB), 256>>>(occ, as_, ae_, out);      // overlaps chain

    cudaStreamWaitEvent(0, e_join, 0);
    k_depadd<<<dim3(16, NB), 256>>>(out, as_, ae_);
}